// round 1
// baseline (speedup 1.0000x reference)
#include <cuda_runtime.h>
#include <cstdint>

#define SQ    2048
#define EB    2048
#define BATCH 2
#define NH    16
#define NKV   4
#define HD    128

// Scratch (device globals — allocation inside kernel_launch is forbidden)
__device__ float g_q[BATCH * SQ * NH * HD];     // 32 MB
__device__ float g_k[BATCH * SQ * NKV * HD];    //  8 MB
__device__ float g_v[BATCH * SQ * NKV * HD];    //  8 MB
__device__ float g_attn[BATCH * SQ * EB];       // 32 MB

// ---------------------------------------------------------------------------
// Classic 128x128x8 SGEMM, 256 threads, 8x8 microtile per thread.
// C[M,N] = A[M,K] @ B[K,N], all row-major, M%128==0, N%128==0, K%8==0.
// ---------------------------------------------------------------------------
__global__ __launch_bounds__(256) void sgemm128(
    const float* __restrict__ A, const float* __restrict__ B,
    float* __restrict__ C, int M, int N, int K)
{
    __shared__ float As[8][128];   // transposed A tile: As[k][m]
    __shared__ float Bs[8][128];

    const int tid = threadIdx.x;
    const int bx = blockIdx.x, by = blockIdx.y;
    const int tx = tid & 15;        // 0..15 -> col group
    const int ty = tid >> 4;        // 0..15 -> row group

    // A tile load mapping: 128 rows x 8 cols, float4 per thread
    const int arow = tid >> 1;          // 0..127
    const int acol = (tid & 1) * 4;     // 0 or 4
    // B tile load mapping: 8 rows x 128 cols
    const int brow = tid >> 5;          // 0..7
    const int bcol = (tid & 31) * 4;

    const float* Aptr = A + (size_t)(by * 128 + arow) * K + acol;
    const float* Bptr = B + (size_t)brow * N + bx * 128 + bcol;

    float acc[8][8];
#pragma unroll
    for (int i = 0; i < 8; i++)
#pragma unroll
        for (int j = 0; j < 8; j++) acc[i][j] = 0.f;

    for (int kt = 0; kt < K; kt += 8) {
        float4 a = *(const float4*)(Aptr + kt);
        As[acol + 0][arow] = a.x;
        As[acol + 1][arow] = a.y;
        As[acol + 2][arow] = a.z;
        As[acol + 3][arow] = a.w;
        float4 b = *(const float4*)(Bptr + (size_t)kt * N);
        *(float4*)&Bs[brow][bcol] = b;
        __syncthreads();

#pragma unroll
        for (int k = 0; k < 8; k++) {
            float ar[8], br[8];
#pragma unroll
            for (int i = 0; i < 8; i++) ar[i] = As[k][ty * 8 + i];
#pragma unroll
            for (int j = 0; j < 8; j++) br[j] = Bs[k][tx * 8 + j];
#pragma unroll
            for (int i = 0; i < 8; i++)
#pragma unroll
                for (int j = 0; j < 8; j++) acc[i][j] += ar[i] * br[j];
        }
        __syncthreads();
    }

#pragma unroll
    for (int i = 0; i < 8; i++) {
        float* crow = C + (size_t)(by * 128 + ty * 8 + i) * N + bx * 128 + tx * 8;
        float4 v0 = make_float4(acc[i][0], acc[i][1], acc[i][2], acc[i][3]);
        float4 v1 = make_float4(acc[i][4], acc[i][5], acc[i][6], acc[i][7]);
        *(float4*)crow = v0;
        *(float4*)(crow + 4) = v1;
    }
}

// ---------------------------------------------------------------------------
// RoPE on q (folds in 1/sqrt(HD) scale) and k, in place.
// q: [B,S,NH,HD], k: [B,S,NKV,HD]. One thread per (d<64) rotation pair.
// ---------------------------------------------------------------------------
__global__ void rope_kernel(float* __restrict__ q, float* __restrict__ k)
{
    const int NQ = BATCH * SQ * NH * 64;
    const int NK = BATCH * SQ * NKV * 64;
    int i = blockIdx.x * blockDim.x + threadIdx.x;
    if (i >= NQ + NK) return;

    float* base;
    int d, s;
    float scale;
    if (i < NQ) {
        d = i & 63;
        int rest = i >> 6;                 // (b*SQ+s)*NH + h
        s = (rest >> 4) & (SQ - 1);
        base = q + (size_t)rest * HD;
        scale = 0.08838834764831845f;      // 1/sqrt(128)
    } else {
        int j = i - NQ;
        d = j & 63;
        int rest = j >> 6;                 // (b*SQ+s)*NKV + kvh
        s = (rest >> 2) & (SQ - 1);
        base = k + (size_t)rest * HD;
        scale = 1.0f;
    }
    float inv_freq = powf(10000.0f, -(float)d * (1.0f / 64.0f));
    float ang = (float)s * inv_freq;
    float c = cosf(ang), sn = sinf(ang);
    float a = base[d], b = base[d + 64];
    base[d]      = (a * c - b * sn) * scale;
    base[d + 64] = (b * c + a * sn) * scale;
}

// ---------------------------------------------------------------------------
// Flash-style causal GQA attention.
// Grid: (S/64, NH, B). 256 threads. Each CTA: 64 q rows of one head.
// Thread layout: r = tid>>2 (row 0..63), quad = tid&3.
//   - scores: thread computes keys {quad + 4*kk}, kk=0..15 (conflict-free Ks reads)
//   - PV:     thread owns float4 cols {4*x8 + quad}, x8=0..7 (conflict-free Vs reads)
// smem: Qs[64][132], Ks[64][132], Vs[64][128], Ps[64][68]  = 117760 B
// q pre-scaled by 1/sqrt(HD) in rope_kernel.
// ---------------------------------------------------------------------------
__global__ __launch_bounds__(256) void attn_kernel(
    const float* __restrict__ q, const float* __restrict__ k,
    const float* __restrict__ v, float* __restrict__ out)
{
    extern __shared__ float sm[];
    float* Qs = sm;                       // 64*132
    float* Ks = Qs + 64 * 132;            // 64*132
    float* Vs = Ks + 64 * 132;            // 64*128
    float* Ps = Vs + 64 * 128;            // 64*68

    float4* Qs4 = (float4*)Qs;            // row stride 33
    float4* Ks4 = (float4*)Ks;            // row stride 33
    float4* Vs4 = (float4*)Vs;            // row stride 32

    const int tid = threadIdx.x;
    const int bxq = blockIdx.x, h = blockIdx.y, b = blockIdx.z;
    const int kvh = h >> 2;               // NH/NKV = 4
    const int q0 = bxq * 64;
    const int r = tid >> 2;
    const int quad = tid & 3;
    const int qg = q0 + r;

    const float4* q4 = (const float4*)q;
    const float4* k4 = (const float4*)k;
    const float4* v4 = (const float4*)v;

    // Load Q tile (64 rows x 32 float4)
#pragma unroll
    for (int i = 0; i < 8; i++) {
        int fl = i * 256 + tid;
        int row = fl >> 5, c = fl & 31;
        Qs4[row * 33 + c] = q4[((size_t)(b * SQ + q0 + row) * NH + h) * 32 + c];
    }

    float o[32];
#pragma unroll
    for (int j = 0; j < 32; j++) o[j] = 0.f;
    float m = -1e30f, l = 0.f;

    for (int kt = 0; kt <= bxq; kt++) {
        const int k0 = kt * 64;
        __syncthreads();   // previous-iter readers of Ks/Vs/Ps done (also covers Q load)
#pragma unroll
        for (int i = 0; i < 8; i++) {
            int fl = i * 256 + tid;
            int row = fl >> 5, c = fl & 31;
            size_t g = ((size_t)(b * SQ + k0 + row) * NKV + kvh) * 32 + c;
            Ks4[row * 33 + c] = k4[g];
            Vs4[row * 32 + c] = v4[g];
        }
        __syncthreads();

        // ---- scores for 16 keys: key = quad + 4*kk ----
        float s[16];
#pragma unroll
        for (int kk = 0; kk < 16; kk++) s[kk] = 0.f;
#pragma unroll 4
        for (int dd = 0; dd < 32; dd++) {
            float4 qv = Qs4[r * 33 + dd];
#pragma unroll
            for (int kk = 0; kk < 16; kk++) {
                float4 kv = Ks4[(quad + 4 * kk) * 33 + dd];
                s[kk] += qv.x * kv.x + qv.y * kv.y + qv.z * kv.z + qv.w * kv.w;
            }
        }

        // causal mask + tile max
        float tmax = -1e30f;
#pragma unroll
        for (int kk = 0; kk < 16; kk++) {
            if (k0 + quad + 4 * kk > qg) s[kk] = -1e30f;
            tmax = fmaxf(tmax, s[kk]);
        }
        tmax = fmaxf(tmax, __shfl_xor_sync(0xffffffffu, tmax, 1));
        tmax = fmaxf(tmax, __shfl_xor_sync(0xffffffffu, tmax, 2));

        float mn = fmaxf(m, tmax);
        float alpha = __expf(m - mn);
        float lsum = 0.f;
#pragma unroll
        for (int kk = 0; kk < 16; kk++) {
            float p = __expf(s[kk] - mn);
            s[kk] = p;
            lsum += p;
        }
        lsum += __shfl_xor_sync(0xffffffffu, lsum, 1);
        lsum += __shfl_xor_sync(0xffffffffu, lsum, 2);
        l = l * alpha + lsum;
        m = mn;
#pragma unroll
        for (int j = 0; j < 32; j++) o[j] *= alpha;

        // publish P row-chunks to smem so each thread can read all 64 keys
#pragma unroll
        for (int kk = 0; kk < 16; kk++) Ps[r * 68 + quad + 4 * kk] = s[kk];
        __syncthreads();

        // ---- PV: o[., cols {4*x8+quad}] += P[r][key] * V[key][cols] ----
#pragma unroll 2
        for (int key = 0; key < 64; key++) {
            float p = Ps[r * 68 + key];
#pragma unroll
            for (int x8 = 0; x8 < 8; x8++) {
                float4 vv = Vs4[key * 32 + 4 * x8 + quad];
                o[4 * x8 + 0] += p * vv.x;
                o[4 * x8 + 1] += p * vv.y;
                o[4 * x8 + 2] += p * vv.z;
                o[4 * x8 + 3] += p * vv.w;
            }
        }
    }

    const float inv_l = 1.0f / l;
    float4* out4 = (float4*)out;
#pragma unroll
    for (int x8 = 0; x8 < 8; x8++) {
        float4 vv = make_float4(o[4 * x8 + 0] * inv_l, o[4 * x8 + 1] * inv_l,
                                o[4 * x8 + 2] * inv_l, o[4 * x8 + 3] * inv_l);
        size_t off = ((size_t)(b * SQ + qg) * EB + h * HD) >> 2;  // float4 units
        out4[off + 4 * x8 + quad] = vv;
    }
}

// ---------------------------------------------------------------------------
extern "C" void kernel_launch(void* const* d_in, const int* in_sizes, int n_in,
                              void* d_out, int out_size)
{
    const float* x  = (const float*)d_in[0];
    const float* Wq = (const float*)d_in[1];
    const float* Wk = (const float*)d_in[2];
    const float* Wv = (const float*)d_in[3];
    const float* Wo = (const float*)d_in[4];

    float *qb, *kb, *vb, *ab;
    cudaGetSymbolAddress((void**)&qb, g_q);
    cudaGetSymbolAddress((void**)&kb, g_k);
    cudaGetSymbolAddress((void**)&vb, g_v);
    cudaGetSymbolAddress((void**)&ab, g_attn);

    const int M = BATCH * SQ;   // 4096

    // Projections
    sgemm128<<<dim3(EB / 128, M / 128), 256>>>(x, Wq, qb, M, EB, EB);
    sgemm128<<<dim3((NKV * HD) / 128, M / 128), 256>>>(x, Wk, kb, M, NKV * HD, EB);
    sgemm128<<<dim3((NKV * HD) / 128, M / 128), 256>>>(x, Wv, vb, M, NKV * HD, EB);

    // RoPE (+ q scaling)
    int npairs = BATCH * SQ * (NH + NKV) * 64;
    rope_kernel<<<(npairs + 255) / 256, 256>>>(qb, kb);

    // Attention
    size_t smem = (size_t)(64 * 132 * 2 + 64 * 128 + 64 * 68) * sizeof(float); // 117760
    cudaFuncSetAttribute(attn_kernel, cudaFuncAttributeMaxDynamicSharedMemorySize,
                         (int)smem);
    attn_kernel<<<dim3(SQ / 64, NH, BATCH), 256, smem>>>(qb, kb, vb, ab);

    // Output projection
    sgemm128<<<dim3(EB / 128, M / 128), 256>>>(ab, Wo, (float*)d_out, M, EB, EB);
}

// round 3
// speedup vs baseline: 1.7611x; 1.7611x over previous
#include <cuda_runtime.h>
#include <cstdint>

#define SQ    2048
#define EB    2048
#define BATCH 2
#define NH    16
#define NKV   4
#define HD    128
#define KVDIM (NKV*HD)

// Scratch (device globals — allocation inside kernel_launch is forbidden)
__device__ float g_q[BATCH * SQ * NH * HD];     // 32 MB
__device__ float g_k[BATCH * SQ * NKV * HD];    //  8 MB
__device__ float g_v[BATCH * SQ * NKV * HD];    //  8 MB
__device__ float g_attn[BATCH * SQ * EB];       // 32 MB
__device__ float g_wt[EB * EB];                 // 16 MB (fragment-packed weight)

// ---------------------------------------------------------------------------
__device__ __forceinline__ uint32_t smem_u32(const void* p) {
    uint32_t a;
    asm("{ .reg .u64 t; cvta.to.shared.u64 t, %1; cvt.u32.u64 %0, t; }"
        : "=r"(a) : "l"(p));
    return a;
}

__device__ __forceinline__ uint32_t to_tf32(float x) {
    uint32_t r;
    asm("cvt.rna.tf32.f32 %0, %1;" : "=r"(r) : "f"(x));
    return r;
}

__device__ __forceinline__ uint4 cvt4(float4 v) {
    uint4 u;
    u.x = to_tf32(v.x); u.y = to_tf32(v.y);
    u.z = to_tf32(v.z); u.w = to_tf32(v.w);
    return u;
}

__device__ __forceinline__ void cp_async16(uint32_t smem_addr, const void* gptr) {
    asm volatile("cp.async.cg.shared.global [%0], [%1], 16;"
                 :: "r"(smem_addr), "l"(gptr));
}

__device__ __forceinline__ void mma168(float4& d, const uint32_t* a, uint2 b) {
    asm volatile(
        "mma.sync.aligned.m16n8k8.row.col.f32.tf32.tf32.f32 "
        "{%0,%1,%2,%3}, {%4,%5,%6,%7}, {%8,%9}, {%0,%1,%2,%3};"
        : "+f"(d.x), "+f"(d.y), "+f"(d.z), "+f"(d.w)
        : "r"(a[0]), "r"(a[1]), "r"(a[2]), "r"(a[3]), "r"(b.x), "r"(b.y));
}

// ---------------------------------------------------------------------------
// Pack W[k][n] (row-major KxN fp32) into per-fragment tf32 layout:
// float2 index gid = (((np*KC + kc)*16 + nt)*4 + ks)*32 + t
//   n = np*128 + nt*8 + t/4 ; k = kc*32 + ks*8 + t%4 ; pair = (B[k][n], B[k+4][n])
// ---------------------------------------------------------------------------
__global__ void pack_b(const float* __restrict__ W, float* __restrict__ Bp,
                       int K, int N)
{
    int gid = blockIdx.x * blockDim.x + threadIdx.x;
    int total = (K * N) >> 1;
    if (gid >= total) return;
    const int KC = K / 32;
    int t  = gid & 31;
    int ks = (gid >> 5) & 3;
    int nt = (gid >> 7) & 15;
    int kc = (gid >> 11) % KC;
    int np = (gid >> 11) / KC;
    int n = np * 128 + nt * 8 + (t >> 2);
    int k = kc * 32 + ks * 8 + (t & 3);
    float v0 = W[(size_t)k * N + n];
    float v1 = W[(size_t)(k + 4) * N + n];
    ((uint2*)Bp)[gid] = make_uint2(to_tf32(v0), to_tf32(v1));
}

// ---------------------------------------------------------------------------
// TF32 tensor-core GEMM via mma.sync: C[M,N] = A[M,K] @ B[K,N]
// A fp32 row-major (cvt to tf32 at smem store); B pre-packed (pack_b).
// Tile 128x128, K-chunk 32, double-buffered. 256 threads = 8 warps (4m x 2n).
// smem floats: As[2][128*36] @ 0/4608, Bs[2][4096] @ 9216/13312 -> 69632 B
// ---------------------------------------------------------------------------
#define GEMM_SMEM 69632

__global__ __launch_bounds__(256, 2) void gemm_mma(
    const float* __restrict__ A, const float* __restrict__ Bp,
    float* __restrict__ C, int M, int N, int K)
{
    extern __shared__ float sm[];
    const int tid = threadIdx.x;
    const int lane = tid & 31, wid = tid >> 5;
    const int wm = wid & 3, wn = wid >> 2;
    const int tm0 = blockIdx.y * 128, tn0 = blockIdx.x * 128;
    const int np = blockIdx.x;
    const int KC = K / 32;
    const uint32_t sb = smem_u32(sm);

    const int arow_t = tid >> 3;          // +i*32
    const int acol4 = (tid & 7) * 4;

    float4 acc[2][8];
#pragma unroll
    for (int i = 0; i < 2; i++)
#pragma unroll
        for (int j = 0; j < 8; j++) acc[i][j] = make_float4(0.f, 0.f, 0.f, 0.f);

    // ---- prologue: chunk 0 into buffer 0 ----
#pragma unroll
    for (int i = 0; i < 4; i++) {
        float4 v = *(const float4*)(A + (size_t)(tm0 + i * 32 + arow_t) * K + acol4);
        *(uint4*)&sm[(i * 32 + arow_t) * 36 + acol4] = cvt4(v);
        cp_async16(sb + (9216 + (i * 256 + tid) * 4) * 4,
                   Bp + ((size_t)np * KC) * 4096 + (i * 256 + tid) * 4);
    }
    asm volatile("cp.async.commit_group;" ::: "memory");
    asm volatile("cp.async.wait_group 0;" ::: "memory");
    __syncthreads();

    for (int c = 0; c < KC; c++) {
        const int cur = c & 1;
        const bool pf = (c + 1 < KC);
        const uint32_t* As32 = (const uint32_t*)(sm + cur * 4608);
        const float* Bsc = sm + 9216 + cur * 4096;

        uint4 pa[4];
        if (pf) {
#pragma unroll
            for (int i = 0; i < 4; i++) {
                float4 v = *(const float4*)(A + (size_t)(tm0 + i * 32 + arow_t) * K +
                                            (c + 1) * 32 + acol4);
                pa[i] = cvt4(v);
                cp_async16(sb + (9216 + (cur ^ 1) * 4096 + (i * 256 + tid) * 4) * 4,
                           Bp + ((size_t)np * KC + (c + 1)) * 4096 + (i * 256 + tid) * 4);
            }
            asm volatile("cp.async.commit_group;" ::: "memory");
        }

#pragma unroll
        for (int ks = 0; ks < 4; ks++) {
            uint32_t af[2][4];
            const int r0 = wm * 32 + (lane >> 2);
            const int c0 = ks * 8 + (lane & 3);
#pragma unroll
            for (int mt = 0; mt < 2; mt++) {
                const int rb = (r0 + mt * 16) * 36;
                af[mt][0] = As32[rb + c0];
                af[mt][1] = As32[rb + 8 * 36 + c0];
                af[mt][2] = As32[rb + c0 + 4];
                af[mt][3] = As32[rb + 8 * 36 + c0 + 4];
            }
#pragma unroll
            for (int nt = 0; nt < 8; nt++) {
                uint2 bf = *(const uint2*)&Bsc[(((wn * 8 + nt) * 4 + ks) * 32 + lane) * 2];
                mma168(acc[0][nt], af[0], bf);
                mma168(acc[1][nt], af[1], bf);
            }
        }

        if (pf) {
#pragma unroll
            for (int i = 0; i < 4; i++)
                *(uint4*)&sm[(cur ^ 1) * 4608 + (i * 32 + arow_t) * 36 + acol4] = pa[i];
            asm volatile("cp.async.wait_group 0;" ::: "memory");
        }
        __syncthreads();
    }

    // ---- epilogue ----
#pragma unroll
    for (int mt = 0; mt < 2; mt++) {
#pragma unroll
        for (int nt = 0; nt < 8; nt++) {
            int row = tm0 + wm * 32 + mt * 16 + (lane >> 2);
            int col = tn0 + wn * 64 + nt * 8 + (lane & 3) * 2;
            float4 a = acc[mt][nt];
            *(float2*)&C[(size_t)row * N + col] = make_float2(a.x, a.y);
            *(float2*)&C[(size_t)(row + 8) * N + col] = make_float2(a.z, a.w);
        }
    }
}

// ---------------------------------------------------------------------------
// RoPE on q (folds in 1/sqrt(HD) scale) and k, in place.
// ---------------------------------------------------------------------------
__global__ void rope_kernel(float* __restrict__ q, float* __restrict__ k)
{
    const int NQ = BATCH * SQ * NH * 64;
    const int NK = BATCH * SQ * NKV * 64;
    int i = blockIdx.x * blockDim.x + threadIdx.x;
    if (i >= NQ + NK) return;

    float* base;
    int d, s;
    float scale;
    if (i < NQ) {
        d = i & 63;
        int rest = i >> 6;
        s = (rest >> 4) & (SQ - 1);
        base = q + (size_t)rest * HD;
        scale = 0.08838834764831845f;
    } else {
        int j = i - NQ;
        d = j & 63;
        int rest = j >> 6;
        s = (rest >> 2) & (SQ - 1);
        base = k + (size_t)rest * HD;
        scale = 1.0f;
    }
    float inv_freq = powf(10000.0f, -(float)d * (1.0f / 64.0f));
    float ang = (float)s * inv_freq;
    float c = cosf(ang), sn = sinf(ang);
    float a = base[d], b = base[d + 64];
    base[d]      = (a * c - b * sn) * scale;
    base[d + 64] = (b * c + a * sn) * scale;
}

// ---------------------------------------------------------------------------
// Flash-style causal GQA attention (unchanged, known-good).
// ---------------------------------------------------------------------------
__global__ __launch_bounds__(256) void attn_kernel(
    const float* __restrict__ q, const float* __restrict__ k,
    const float* __restrict__ v, float* __restrict__ out)
{
    extern __shared__ float smf[];
    float* Qs = smf;
    float* Ks = Qs + 64 * 132;
    float* Vs = Ks + 64 * 132;
    float* Ps = Vs + 64 * 128;

    float4* Qs4 = (float4*)Qs;
    float4* Ks4 = (float4*)Ks;
    float4* Vs4 = (float4*)Vs;

    const int tid = threadIdx.x;
    const int bxq = blockIdx.x, h = blockIdx.y, b = blockIdx.z;
    const int kvh = h >> 2;
    const int q0 = bxq * 64;
    const int r = tid >> 2;
    const int quad = tid & 3;
    const int qg = q0 + r;

    const float4* q4 = (const float4*)q;
    const float4* k4 = (const float4*)k;
    const float4* v4 = (const float4*)v;

#pragma unroll
    for (int i = 0; i < 8; i++) {
        int fl = i * 256 + tid;
        int row = fl >> 5, c = fl & 31;
        Qs4[row * 33 + c] = q4[((size_t)(b * SQ + q0 + row) * NH + h) * 32 + c];
    }

    float o[32];
#pragma unroll
    for (int j = 0; j < 32; j++) o[j] = 0.f;
    float m = -1e30f, l = 0.f;

    for (int kt = 0; kt <= bxq; kt++) {
        const int k0 = kt * 64;
        __syncthreads();
#pragma unroll
        for (int i = 0; i < 8; i++) {
            int fl = i * 256 + tid;
            int row = fl >> 5, c = fl & 31;
            size_t g = ((size_t)(b * SQ + k0 + row) * NKV + kvh) * 32 + c;
            Ks4[row * 33 + c] = k4[g];
            Vs4[row * 32 + c] = v4[g];
        }
        __syncthreads();

        float s[16];
#pragma unroll
        for (int kk = 0; kk < 16; kk++) s[kk] = 0.f;
#pragma unroll 4
        for (int dd = 0; dd < 32; dd++) {
            float4 qv = Qs4[r * 33 + dd];
#pragma unroll
            for (int kk = 0; kk < 16; kk++) {
                float4 kv = Ks4[(quad + 4 * kk) * 33 + dd];
                s[kk] += qv.x * kv.x + qv.y * kv.y + qv.z * kv.z + qv.w * kv.w;
            }
        }

        float tmax = -1e30f;
#pragma unroll
        for (int kk = 0; kk < 16; kk++) {
            if (k0 + quad + 4 * kk > qg) s[kk] = -1e30f;
            tmax = fmaxf(tmax, s[kk]);
        }
        tmax = fmaxf(tmax, __shfl_xor_sync(0xffffffffu, tmax, 1));
        tmax = fmaxf(tmax, __shfl_xor_sync(0xffffffffu, tmax, 2));

        float mn = fmaxf(m, tmax);
        float alpha = __expf(m - mn);
        float lsum = 0.f;
#pragma unroll
        for (int kk = 0; kk < 16; kk++) {
            float p = __expf(s[kk] - mn);
            s[kk] = p;
            lsum += p;
        }
        lsum += __shfl_xor_sync(0xffffffffu, lsum, 1);
        lsum += __shfl_xor_sync(0xffffffffu, lsum, 2);
        l = l * alpha + lsum;
        m = mn;
#pragma unroll
        for (int j = 0; j < 32; j++) o[j] *= alpha;

#pragma unroll
        for (int kk = 0; kk < 16; kk++) Ps[r * 68 + quad + 4 * kk] = s[kk];
        __syncthreads();

#pragma unroll 2
        for (int key = 0; key < 64; key++) {
            float p = Ps[r * 68 + key];
#pragma unroll
            for (int x8 = 0; x8 < 8; x8++) {
                float4 vv = Vs4[key * 32 + 4 * x8 + quad];
                o[4 * x8 + 0] += p * vv.x;
                o[4 * x8 + 1] += p * vv.y;
                o[4 * x8 + 2] += p * vv.z;
                o[4 * x8 + 3] += p * vv.w;
            }
        }
    }

    const float inv_l = 1.0f / l;
    float4* out4 = (float4*)out;
#pragma unroll
    for (int x8 = 0; x8 < 8; x8++) {
        float4 vv = make_float4(o[4 * x8 + 0] * inv_l, o[4 * x8 + 1] * inv_l,
                                o[4 * x8 + 2] * inv_l, o[4 * x8 + 3] * inv_l);
        size_t off = ((size_t)(b * SQ + qg) * EB + h * HD) >> 2;
        out4[off + 4 * x8 + quad] = vv;
    }
}

// ---------------------------------------------------------------------------
extern "C" void kernel_launch(void* const* d_in, const int* in_sizes, int n_in,
                              void* d_out, int out_size)
{
    const float* x  = (const float*)d_in[0];
    const float* Wq = (const float*)d_in[1];
    const float* Wk = (const float*)d_in[2];
    const float* Wv = (const float*)d_in[3];
    const float* Wo = (const float*)d_in[4];

    float *qb, *kb, *vb, *ab, *wt;
    cudaGetSymbolAddress((void**)&qb, g_q);
    cudaGetSymbolAddress((void**)&kb, g_k);
    cudaGetSymbolAddress((void**)&vb, g_v);
    cudaGetSymbolAddress((void**)&ab, g_attn);
    cudaGetSymbolAddress((void**)&wt, g_wt);

    const int M = BATCH * SQ;   // 4096

    cudaFuncSetAttribute(gemm_mma, cudaFuncAttributeMaxDynamicSharedMemorySize,
                         GEMM_SMEM);

    // Q projection
    pack_b<<<(EB * EB / 2 + 255) / 256, 256>>>(Wq, wt, EB, EB);
    gemm_mma<<<dim3(EB / 128, M / 128), 256, GEMM_SMEM>>>(x, wt, qb, M, EB, EB);
    // K projection
    pack_b<<<(EB * KVDIM / 2 + 255) / 256, 256>>>(Wk, wt, EB, KVDIM);
    gemm_mma<<<dim3(KVDIM / 128, M / 128), 256, GEMM_SMEM>>>(x, wt, kb, M, KVDIM, EB);
    // V projection
    pack_b<<<(EB * KVDIM / 2 + 255) / 256, 256>>>(Wv, wt, EB, KVDIM);
    gemm_mma<<<dim3(KVDIM / 128, M / 128), 256, GEMM_SMEM>>>(x, wt, vb, M, KVDIM, EB);

    // RoPE (+ q scaling)
    int npairs = BATCH * SQ * (NH + NKV) * 64;
    rope_kernel<<<(npairs + 255) / 256, 256>>>(qb, kb);

    // Attention
    size_t smem = (size_t)(64 * 132 * 2 + 64 * 128 + 64 * 68) * sizeof(float);
    cudaFuncSetAttribute(attn_kernel, cudaFuncAttributeMaxDynamicSharedMemorySize,
                         (int)smem);
    attn_kernel<<<dim3(SQ / 64, NH, BATCH), 256, smem>>>(qb, kb, vb, ab);

    // Output projection
    pack_b<<<(EB * EB / 2 + 255) / 256, 256>>>(Wo, wt, EB, EB);
    gemm_mma<<<dim3(EB / 128, M / 128), 256, GEMM_SMEM>>>(ab, wt, (float*)d_out, M, EB, EB);
}

// round 4
// speedup vs baseline: 5.6456x; 3.2057x over previous
#include <cuda_runtime.h>
#include <cstdint>

#define SQ    2048
#define EB    2048
#define BATCH 2
#define NH    16
#define NKV   4
#define HD    128
#define KVDIM (NKV*HD)

// Scratch (device globals — allocation inside kernel_launch is forbidden)
__device__ float g_q[BATCH * SQ * NH * HD];     // 32 MB
__device__ float g_k[BATCH * SQ * NKV * HD];    //  8 MB
__device__ float g_v[BATCH * SQ * NKV * HD];    //  8 MB
__device__ float g_attn[BATCH * SQ * EB];       // 32 MB
__device__ float g_wt[EB * 3072];               // 25 MB (fragment-packed weights)

// ---------------------------------------------------------------------------
__device__ __forceinline__ uint32_t smem_u32(const void* p) {
    uint32_t a;
    asm("{ .reg .u64 t; cvta.to.shared.u64 t, %1; cvt.u32.u64 %0, t; }"
        : "=r"(a) : "l"(p));
    return a;
}

__device__ __forceinline__ uint32_t to_tf32(float x) {
    uint32_t r;
    asm("cvt.rna.tf32.f32 %0, %1;" : "=r"(r) : "f"(x));
    return r;
}

__device__ __forceinline__ uint4 cvt4(float4 v) {
    uint4 u;
    u.x = to_tf32(v.x); u.y = to_tf32(v.y);
    u.z = to_tf32(v.z); u.w = to_tf32(v.w);
    return u;
}

__device__ __forceinline__ void cp_async16(uint32_t smem_addr, const void* gptr) {
    asm volatile("cp.async.cg.shared.global [%0], [%1], 16;"
                 :: "r"(smem_addr), "l"(gptr));
}

__device__ __forceinline__ void mma168(float4& d, const uint32_t* a, uint2 b) {
    asm volatile(
        "mma.sync.aligned.m16n8k8.row.col.f32.tf32.tf32.f32 "
        "{%0,%1,%2,%3}, {%4,%5,%6,%7}, {%8,%9}, {%0,%1,%2,%3};"
        : "+f"(d.x), "+f"(d.y), "+f"(d.z), "+f"(d.w)
        : "r"(a[0]), "r"(a[1]), "r"(a[2]), "r"(a[3]), "r"(b.x), "r"(b.y));
}

// ---------------------------------------------------------------------------
// Pack W[k][n] (row-major KxN fp32) into per-fragment tf32 layout.
// ---------------------------------------------------------------------------
__global__ void pack_b(const float* __restrict__ W, float* __restrict__ Bp,
                       int K, int N)
{
    int gid = blockIdx.x * blockDim.x + threadIdx.x;
    int total = (K * N) >> 1;
    if (gid >= total) return;
    const int KC = K / 32;
    int t  = gid & 31;
    int ks = (gid >> 5) & 3;
    int nt = (gid >> 7) & 15;
    int kc = (gid >> 11) % KC;
    int np = (gid >> 11) / KC;
    int n = np * 128 + nt * 8 + (t >> 2);
    int k = kc * 32 + ks * 8 + (t & 3);
    float v0 = W[(size_t)k * N + n];
    float v1 = W[(size_t)(k + 4) * N + n];
    ((uint2*)Bp)[gid] = make_uint2(to_tf32(v0), to_tf32(v1));
}

// ---------------------------------------------------------------------------
// TF32 tensor-core GEMM via mma.sync (known-good from R3) + fused-QKV routing.
// ---------------------------------------------------------------------------
#define GEMM_SMEM 69632

__global__ __launch_bounds__(256, 2) void gemm_mma(
    const float* __restrict__ A, const float* __restrict__ Bp,
    float* __restrict__ C0, float* __restrict__ C1, float* __restrict__ C2,
    int M, int N, int K, int fused)
{
    extern __shared__ float sm[];
    const int tid = threadIdx.x;
    const int lane = tid & 31, wid = tid >> 5;
    const int wm = wid & 3, wn = wid >> 2;
    const int tm0 = blockIdx.y * 128, tn0 = blockIdx.x * 128;
    const int np = blockIdx.x;
    const int KC = K / 32;
    const uint32_t sb = smem_u32(sm);

    const int arow_t = tid >> 3;
    const int acol4 = (tid & 7) * 4;

    float4 acc[2][8];
#pragma unroll
    for (int i = 0; i < 2; i++)
#pragma unroll
        for (int j = 0; j < 8; j++) acc[i][j] = make_float4(0.f, 0.f, 0.f, 0.f);

#pragma unroll
    for (int i = 0; i < 4; i++) {
        float4 v = *(const float4*)(A + (size_t)(tm0 + i * 32 + arow_t) * K + acol4);
        *(uint4*)&sm[(i * 32 + arow_t) * 36 + acol4] = cvt4(v);
        cp_async16(sb + (9216 + (i * 256 + tid) * 4) * 4,
                   Bp + ((size_t)np * KC) * 4096 + (i * 256 + tid) * 4);
    }
    asm volatile("cp.async.commit_group;" ::: "memory");
    asm volatile("cp.async.wait_group 0;" ::: "memory");
    __syncthreads();

    for (int c = 0; c < KC; c++) {
        const int cur = c & 1;
        const bool pf = (c + 1 < KC);
        const uint32_t* As32 = (const uint32_t*)(sm + cur * 4608);
        const float* Bsc = sm + 9216 + cur * 4096;

        uint4 pa[4];
        if (pf) {
#pragma unroll
            for (int i = 0; i < 4; i++) {
                float4 v = *(const float4*)(A + (size_t)(tm0 + i * 32 + arow_t) * K +
                                            (c + 1) * 32 + acol4);
                pa[i] = cvt4(v);
                cp_async16(sb + (9216 + (cur ^ 1) * 4096 + (i * 256 + tid) * 4) * 4,
                           Bp + ((size_t)np * KC + (c + 1)) * 4096 + (i * 256 + tid) * 4);
            }
            asm volatile("cp.async.commit_group;" ::: "memory");
        }

#pragma unroll
        for (int ks = 0; ks < 4; ks++) {
            uint32_t af[2][4];
            const int r0 = wm * 32 + (lane >> 2);
            const int c0 = ks * 8 + (lane & 3);
#pragma unroll
            for (int mt = 0; mt < 2; mt++) {
                const int rb = (r0 + mt * 16) * 36;
                af[mt][0] = As32[rb + c0];
                af[mt][1] = As32[rb + 8 * 36 + c0];
                af[mt][2] = As32[rb + c0 + 4];
                af[mt][3] = As32[rb + 8 * 36 + c0 + 4];
            }
#pragma unroll
            for (int nt = 0; nt < 8; nt++) {
                uint2 bf = *(const uint2*)&Bsc[(((wn * 8 + nt) * 4 + ks) * 32 + lane) * 2];
                mma168(acc[0][nt], af[0], bf);
                mma168(acc[1][nt], af[1], bf);
            }
        }

        if (pf) {
#pragma unroll
            for (int i = 0; i < 4; i++)
                *(uint4*)&sm[(cur ^ 1) * 4608 + (i * 32 + arow_t) * 36 + acol4] = pa[i];
            asm volatile("cp.async.wait_group 0;" ::: "memory");
        }
        __syncthreads();
    }

    // ---- epilogue with fused-QKV routing ----
    float* Cd; int ldc, coff;
    if (!fused)            { Cd = C0; ldc = N;    coff = 0;    }
    else if (tn0 < 2048)   { Cd = C0; ldc = 2048; coff = 0;    }
    else if (tn0 < 2560)   { Cd = C1; ldc = 512;  coff = 2048; }
    else                   { Cd = C2; ldc = 512;  coff = 2560; }

#pragma unroll
    for (int mt = 0; mt < 2; mt++) {
#pragma unroll
        for (int nt = 0; nt < 8; nt++) {
            int row = tm0 + wm * 32 + mt * 16 + (lane >> 2);
            int col = tn0 + wn * 64 + nt * 8 + (lane & 3) * 2 - coff;
            float4 a = acc[mt][nt];
            *(float2*)&Cd[(size_t)row * ldc + col] = make_float2(a.x, a.y);
            *(float2*)&Cd[(size_t)(row + 8) * ldc + col] = make_float2(a.z, a.w);
        }
    }
}

// ---------------------------------------------------------------------------
// RoPE on q (folds in 1/sqrt(HD) scale) and k, in place.
// ---------------------------------------------------------------------------
__global__ void rope_kernel(float* __restrict__ q, float* __restrict__ k)
{
    const int NQ = BATCH * SQ * NH * 64;
    const int NK = BATCH * SQ * NKV * 64;
    int i = blockIdx.x * blockDim.x + threadIdx.x;
    if (i >= NQ + NK) return;

    float* base;
    int d, s;
    float scale;
    if (i < NQ) {
        d = i & 63;
        int rest = i >> 6;
        s = (rest >> 4) & (SQ - 1);
        base = q + (size_t)rest * HD;
        scale = 0.08838834764831845f;
    } else {
        int j = i - NQ;
        d = j & 63;
        int rest = j >> 6;
        s = (rest >> 2) & (SQ - 1);
        base = k + (size_t)rest * HD;
        scale = 1.0f;
    }
    float inv_freq = powf(10000.0f, -(float)d * (1.0f / 64.0f));
    float ang = (float)s * inv_freq;
    float c = cosf(ang), sn = sinf(ang);
    float a = base[d], b = base[d + 64];
    base[d]      = (a * c - b * sn) * scale;
    base[d + 64] = (b * c + a * sn) * scale;
}

// ---------------------------------------------------------------------------
// Tensor-core flash attention (tf32 mma). CTA: 128 q-rows x one (b,h).
// 8 warps: wm=wid&3 (32 rows each), wn=wid>>2 (key/val halves).
// Fragment smem strides (conflict-free): Q/K 132, V 136, P 68.
// ---------------------------------------------------------------------------
#define QS_OFF 0                // 128*132 tf32
#define KS_OFF 16896            // 64*132
#define VS_OFF 25344            // 64*136
#define PS_OFF 34048            // 128*68
#define MB_OFF 42752            // 2*128 (per-wn row max)
#define LB_OFF 43008            // 2*128 (per-wn row sum)
#define ATT_SMEM (43264 * 4)    // 173056 B

__global__ __launch_bounds__(256, 1) void attn_mma(
    const float* __restrict__ q, const float* __restrict__ k,
    const float* __restrict__ v, float* __restrict__ out)
{
    extern __shared__ float sm[];
    uint32_t* smu = (uint32_t*)sm;
    const int tid = threadIdx.x;
    const int lane = tid & 31, wid = tid >> 5;
    const int g = lane >> 2, t = lane & 3;
    const int wm = wid & 3, wn = wid >> 2;
    const int bxq = blockIdx.x, h = blockIdx.y, b = blockIdx.z;
    const int kvh = h >> 2;
    const int q0 = bxq * 128;

    // Q tile 128x128 -> tf32, stride 132
#pragma unroll
    for (int i = 0; i < 16; i++) {
        int f = i * 256 + tid;
        int row = f >> 5, c = f & 31;
        float4 vv = *(const float4*)(q + ((size_t)(b * SQ + q0 + row) * NH + h) * HD + c * 4);
        *(uint4*)&smu[QS_OFF + row * 132 + c * 4] = cvt4(vv);
    }

    float4 oacc[2][8];
#pragma unroll
    for (int i = 0; i < 2; i++)
#pragma unroll
        for (int j = 0; j < 8; j++) oacc[i][j] = make_float4(0.f, 0.f, 0.f, 0.f);
    float m_s[2][2] = {{-1e30f, -1e30f}, {-1e30f, -1e30f}};
    float l_s[2][2] = {{0.f, 0.f}, {0.f, 0.f}};

    const int r0 = wm * 32 + g;
    const int ntiles = 2 * bxq + 2;

    for (int kt = 0; kt < ntiles; kt++) {
        const int k0 = kt * 64;
        __syncthreads();   // prev-iter smem consumers done
#pragma unroll
        for (int i = 0; i < 8; i++) {
            int f = i * 256 + tid;
            int row = f >> 5, c = f & 31;
            size_t gi = ((size_t)(b * SQ + k0 + row) * NKV + kvh) * HD + c * 4;
            *(uint4*)&smu[KS_OFF + row * 132 + c * 4] = cvt4(*(const float4*)(k + gi));
            *(uint4*)&smu[VS_OFF + row * 136 + c * 4] = cvt4(*(const float4*)(v + gi));
        }
        __syncthreads();

        // ---- S = Q @ K^T (rows: wm, keys: wn*32 + nt*8) ----
        float4 sacc[2][4];
#pragma unroll
        for (int i = 0; i < 2; i++)
#pragma unroll
            for (int j = 0; j < 4; j++) sacc[i][j] = make_float4(0.f, 0.f, 0.f, 0.f);

#pragma unroll
        for (int ks = 0; ks < 16; ks++) {
            const int c0 = ks * 8 + t;
            uint32_t af[2][4];
#pragma unroll
            for (int mt = 0; mt < 2; mt++) {
                int rb = QS_OFF + (r0 + mt * 16) * 132 + c0;
                af[mt][0] = smu[rb];
                af[mt][1] = smu[rb + 132 * 8];
                af[mt][2] = smu[rb + 4];
                af[mt][3] = smu[rb + 132 * 8 + 4];
            }
#pragma unroll
            for (int nt = 0; nt < 4; nt++) {
                int nb = KS_OFF + (wn * 32 + nt * 8 + g) * 132 + c0;
                uint2 bf = make_uint2(smu[nb], smu[nb + 4]);
                mma168(sacc[0][nt], af[0], bf);
                mma168(sacc[1][nt], af[1], bf);
            }
        }

        // ---- causal mask (diagonal tiles only) ----
        if (kt >= 2 * bxq) {
#pragma unroll
            for (int mt = 0; mt < 2; mt++)
#pragma unroll
                for (int nt = 0; nt < 4; nt++) {
                    int colb = k0 + wn * 32 + nt * 8 + 2 * t;
                    int rowb = q0 + wm * 32 + mt * 16 + g;
                    float* sc = (float*)&sacc[mt][nt];
                    if (colb     > rowb)     sc[0] = -1e30f;
                    if (colb + 1 > rowb)     sc[1] = -1e30f;
                    if (colb     > rowb + 8) sc[2] = -1e30f;
                    if (colb + 1 > rowb + 8) sc[3] = -1e30f;
                }
        }

        // ---- row max (thread -> quad shfl -> cross-warp smem) ----
        float rmax[2][2] = {{-1e30f, -1e30f}, {-1e30f, -1e30f}};
#pragma unroll
        for (int mt = 0; mt < 2; mt++)
#pragma unroll
            for (int nt = 0; nt < 4; nt++) {
                float4 s4 = sacc[mt][nt];
                rmax[mt][0] = fmaxf(rmax[mt][0], fmaxf(s4.x, s4.y));
                rmax[mt][1] = fmaxf(rmax[mt][1], fmaxf(s4.z, s4.w));
            }
#pragma unroll
        for (int mt = 0; mt < 2; mt++)
#pragma unroll
            for (int hf = 0; hf < 2; hf++) {
                float x = rmax[mt][hf];
                x = fmaxf(x, __shfl_xor_sync(0xffffffffu, x, 1));
                x = fmaxf(x, __shfl_xor_sync(0xffffffffu, x, 2));
                rmax[mt][hf] = x;
            }
        if (t == 0) {
#pragma unroll
            for (int mt = 0; mt < 2; mt++)
#pragma unroll
                for (int hf = 0; hf < 2; hf++)
                    sm[MB_OFF + wn * 128 + wm * 32 + mt * 16 + hf * 8 + g] = rmax[mt][hf];
        }
        __syncthreads();

        float alpha[2][2];
#pragma unroll
        for (int mt = 0; mt < 2; mt++)
#pragma unroll
            for (int hf = 0; hf < 2; hf++) {
                int row = wm * 32 + mt * 16 + hf * 8 + g;
                float mn = fmaxf(m_s[mt][hf],
                                 fmaxf(sm[MB_OFF + row], sm[MB_OFF + 128 + row]));
                alpha[mt][hf] = __expf(m_s[mt][hf] - mn);
                m_s[mt][hf] = mn;
            }

        // ---- P = exp(S - m), row sums, publish P (tf32) ----
        float rsum[2][2] = {{0.f, 0.f}, {0.f, 0.f}};
#pragma unroll
        for (int mt = 0; mt < 2; mt++)
#pragma unroll
            for (int nt = 0; nt < 4; nt++) {
                float4 s4 = sacc[mt][nt];
                float p0 = __expf(s4.x - m_s[mt][0]);
                float p1 = __expf(s4.y - m_s[mt][0]);
                float p2 = __expf(s4.z - m_s[mt][1]);
                float p3 = __expf(s4.w - m_s[mt][1]);
                rsum[mt][0] += p0 + p1;
                rsum[mt][1] += p2 + p3;
                int cb = wn * 32 + nt * 8 + 2 * t;
                int rl = wm * 32 + mt * 16 + g;
                *(uint2*)&smu[PS_OFF + rl * 68 + cb] =
                    make_uint2(to_tf32(p0), to_tf32(p1));
                *(uint2*)&smu[PS_OFF + (rl + 8) * 68 + cb] =
                    make_uint2(to_tf32(p2), to_tf32(p3));
            }
#pragma unroll
        for (int mt = 0; mt < 2; mt++)
#pragma unroll
            for (int hf = 0; hf < 2; hf++) {
                float x = rsum[mt][hf];
                x += __shfl_xor_sync(0xffffffffu, x, 1);
                x += __shfl_xor_sync(0xffffffffu, x, 2);
                rsum[mt][hf] = x;
            }
        if (t == 0) {
#pragma unroll
            for (int mt = 0; mt < 2; mt++)
#pragma unroll
                for (int hf = 0; hf < 2; hf++)
                    sm[LB_OFF + wn * 128 + wm * 32 + mt * 16 + hf * 8 + g] = rsum[mt][hf];
        }
        // rescale O by alpha
#pragma unroll
        for (int mt = 0; mt < 2; mt++)
#pragma unroll
            for (int nt = 0; nt < 8; nt++) {
                oacc[mt][nt].x *= alpha[mt][0];
                oacc[mt][nt].y *= alpha[mt][0];
                oacc[mt][nt].z *= alpha[mt][1];
                oacc[mt][nt].w *= alpha[mt][1];
            }
        __syncthreads();
#pragma unroll
        for (int mt = 0; mt < 2; mt++)
#pragma unroll
            for (int hf = 0; hf < 2; hf++) {
                int row = wm * 32 + mt * 16 + hf * 8 + g;
                l_s[mt][hf] = l_s[mt][hf] * alpha[mt][hf]
                            + sm[LB_OFF + row] + sm[LB_OFF + 128 + row];
            }

        // ---- O += P @ V (d cols: wn*64 + nt*8; V read transposed-scalar) ----
#pragma unroll
        for (int ks = 0; ks < 8; ks++) {
            const int c0 = ks * 8 + t;
            uint32_t af[2][4];
#pragma unroll
            for (int mt = 0; mt < 2; mt++) {
                int rb = PS_OFF + (r0 + mt * 16) * 68 + c0;
                af[mt][0] = smu[rb];
                af[mt][1] = smu[rb + 68 * 8];
                af[mt][2] = smu[rb + 4];
                af[mt][3] = smu[rb + 68 * 8 + 4];
            }
#pragma unroll
            for (int nt = 0; nt < 8; nt++) {
                int nb = VS_OFF + c0 * 136 + wn * 64 + nt * 8 + g;
                uint2 bf = make_uint2(smu[nb], smu[nb + 4 * 136]);
                mma168(oacc[0][nt], af[0], bf);
                mma168(oacc[1][nt], af[1], bf);
            }
        }
    }

    // ---- epilogue: O / l -> out[b][row][h*128 + col] ----
#pragma unroll
    for (int mt = 0; mt < 2; mt++) {
        float i0 = 1.f / l_s[mt][0], i1 = 1.f / l_s[mt][1];
#pragma unroll
        for (int nt = 0; nt < 8; nt++) {
            int row = q0 + wm * 32 + mt * 16 + g;
            int col = h * HD + wn * 64 + nt * 8 + 2 * t;
            float4 o = oacc[mt][nt];
            *(float2*)&out[(size_t)(b * SQ + row) * EB + col] =
                make_float2(o.x * i0, o.y * i0);
            *(float2*)&out[(size_t)(b * SQ + row + 8) * EB + col] =
                make_float2(o.z * i1, o.w * i1);
        }
    }
}

// ---------------------------------------------------------------------------
extern "C" void kernel_launch(void* const* d_in, const int* in_sizes, int n_in,
                              void* d_out, int out_size)
{
    const float* x  = (const float*)d_in[0];
    const float* Wq = (const float*)d_in[1];
    const float* Wk = (const float*)d_in[2];
    const float* Wv = (const float*)d_in[3];
    const float* Wo = (const float*)d_in[4];

    float *qb, *kb, *vb, *ab, *wt;
    cudaGetSymbolAddress((void**)&qb, g_q);
    cudaGetSymbolAddress((void**)&kb, g_k);
    cudaGetSymbolAddress((void**)&vb, g_v);
    cudaGetSymbolAddress((void**)&ab, g_attn);
    cudaGetSymbolAddress((void**)&wt, g_wt);

    const int M = BATCH * SQ;   // 4096

    cudaFuncSetAttribute(gemm_mma, cudaFuncAttributeMaxDynamicSharedMemorySize,
                         GEMM_SMEM);
    cudaFuncSetAttribute(attn_mma, cudaFuncAttributeMaxDynamicSharedMemorySize,
                         ATT_SMEM);

    // Pack Q|K|V weights into one fragment buffer (np blocks of 128 cols)
    pack_b<<<(EB * EB / 2 + 255) / 256, 256>>>(Wq, wt, EB, EB);
    pack_b<<<(EB * KVDIM / 2 + 255) / 256, 256>>>(Wk, wt + 16 * 262144, EB, KVDIM);
    pack_b<<<(EB * KVDIM / 2 + 255) / 256, 256>>>(Wv, wt + 20 * 262144, EB, KVDIM);

    // Fused QKV projection: N = 2048 + 512 + 512 = 3072
    gemm_mma<<<dim3(3072 / 128, M / 128), 256, GEMM_SMEM>>>(
        x, wt, qb, kb, vb, M, 3072, EB, 1);

    // RoPE (+ q scaling)
    int npairs = BATCH * SQ * (NH + NKV) * 64;
    rope_kernel<<<(npairs + 255) / 256, 256>>>(qb, kb);

    // Tensor-core flash attention
    attn_mma<<<dim3(SQ / 128, NH, BATCH), 256, ATT_SMEM>>>(qb, kb, vb, ab);

    // Output projection
    pack_b<<<(EB * EB / 2 + 255) / 256, 256>>>(Wo, wt, EB, EB);
    gemm_mma<<<dim3(EB / 128, M / 128), 256, GEMM_SMEM>>>(
        ab, wt, (float*)d_out, nullptr, nullptr, M, EB, EB, 0);
}

// round 6
// speedup vs baseline: 5.8034x; 1.0279x over previous
#include <cuda_runtime.h>
#include <cstdint>

#define SQ    2048
#define EB    2048
#define BATCH 2
#define NH    16
#define NKV   4
#define HD    128
#define KVDIM (NKV*HD)

// Scratch (device globals — allocation inside kernel_launch is forbidden)
__device__ float g_q[BATCH * SQ * NH * HD];     // 32 MB
__device__ float g_k[BATCH * SQ * NKV * HD];    //  8 MB
__device__ float g_v[BATCH * SQ * NKV * HD];    //  8 MB
__device__ float g_attn[BATCH * SQ * EB];       // 32 MB
__device__ float g_wt[EB * 3072];               // 25 MB (fragment-packed weights)

// ---------------------------------------------------------------------------
__device__ __forceinline__ uint32_t smem_u32(const void* p) {
    uint32_t a;
    asm("{ .reg .u64 t; cvta.to.shared.u64 t, %1; cvt.u32.u64 %0, t; }"
        : "=r"(a) : "l"(p));
    return a;
}

__device__ __forceinline__ uint32_t to_tf32(float x) {
    uint32_t r;
    asm("cvt.rna.tf32.f32 %0, %1;" : "=r"(r) : "f"(x));
    return r;
}

__device__ __forceinline__ uint4 cvt4(float4 v) {
    uint4 u;
    u.x = to_tf32(v.x); u.y = to_tf32(v.y);
    u.z = to_tf32(v.z); u.w = to_tf32(v.w);
    return u;
}

__device__ __forceinline__ void cp_async16(uint32_t smem_addr, const void* gptr) {
    asm volatile("cp.async.cg.shared.global [%0], [%1], 16;"
                 :: "r"(smem_addr), "l"(gptr));
}

__device__ __forceinline__ void mma168(float4& d, const uint32_t* a, uint2 b) {
    asm volatile(
        "mma.sync.aligned.m16n8k8.row.col.f32.tf32.tf32.f32 "
        "{%0,%1,%2,%3}, {%4,%5,%6,%7}, {%8,%9}, {%0,%1,%2,%3};"
        : "+f"(d.x), "+f"(d.y), "+f"(d.z), "+f"(d.w)
        : "r"(a[0]), "r"(a[1]), "r"(a[2]), "r"(a[3]), "r"(b.x), "r"(b.y));
}

// ---------------------------------------------------------------------------
// Pack W[k][n] (row-major KxN fp32) into per-fragment tf32 layout.
// ---------------------------------------------------------------------------
__global__ void pack_b(const float* __restrict__ W, float* __restrict__ Bp,
                       int K, int N)
{
    int gid = blockIdx.x * blockDim.x + threadIdx.x;
    int total = (K * N) >> 1;
    if (gid >= total) return;
    const int KC = K / 32;
    int t  = gid & 31;
    int ks = (gid >> 5) & 3;
    int nt = (gid >> 7) & 15;
    int kc = (gid >> 11) % KC;
    int np = (gid >> 11) / KC;
    int n = np * 128 + nt * 8 + (t >> 2);
    int k = kc * 32 + ks * 8 + (t & 3);
    float v0 = W[(size_t)k * N + n];
    float v1 = W[(size_t)(k + 4) * N + n];
    ((uint2*)Bp)[gid] = make_uint2(to_tf32(v0), to_tf32(v1));
}

// ---------------------------------------------------------------------------
// TF32 GEMM v2: C[M,N] = A[M,K] @ B[K,N].
// CTA tile 256x128, 8 warps (wm=wid&3 over 4 m-blocks of 64, wn=wid>>2).
// Warp tile 64x64 (mt=4, nt=8). 4-stage cp.async pipeline.
// ---------------------------------------------------------------------------
#define GEMM_SMEM 212992
#define GST 13312

__device__ __forceinline__ void gemm_issue(
    const float* __restrict__ A, const float* __restrict__ Bp,
    uint32_t sb, int c, int tm0, int np, int K, int KC, int tid)
{
    const int st = c & 3;
    const uint32_t ab = sb + (st * GST) * 4;
    const uint32_t bb = sb + (st * GST + 9216) * 4;
    const int row = tid >> 3, col4 = (tid & 7) * 4;
#pragma unroll
    for (int i = 0; i < 8; i++)
        cp_async16(ab + ((i * 32 + row) * 36 + col4) * 4,
                   A + (size_t)(tm0 + i * 32 + row) * K + c * 32 + col4);
#pragma unroll
    for (int i = 0; i < 4; i++)
        cp_async16(bb + (i * 256 + tid) * 16,
                   Bp + ((size_t)np * KC + c) * 4096 + (i * 256 + tid) * 4);
    asm volatile("cp.async.commit_group;" ::: "memory");
}

__global__ __launch_bounds__(256, 1) void gemm_mma(
    const float* __restrict__ A, const float* __restrict__ Bp,
    float* __restrict__ C0, float* __restrict__ C1, float* __restrict__ C2,
    int M, int N, int K, int fused)
{
    extern __shared__ float sm[];
    const int tid = threadIdx.x;
    const int lane = tid & 31, wid = tid >> 5;
    const int g = lane >> 2, t = lane & 3;
    const int wm = wid & 3, wn = wid >> 2;
    const int tm0 = blockIdx.y * 256, tn0 = blockIdx.x * 128;
    const int np = blockIdx.x;
    const int KC = K / 32;
    const uint32_t sb = smem_u32(sm);

    float4 acc[4][8];
#pragma unroll
    for (int i = 0; i < 4; i++)
#pragma unroll
        for (int j = 0; j < 8; j++) acc[i][j] = make_float4(0.f, 0.f, 0.f, 0.f);

    gemm_issue(A, Bp, sb, 0, tm0, np, K, KC, tid);
    gemm_issue(A, Bp, sb, 1, tm0, np, K, KC, tid);
    gemm_issue(A, Bp, sb, 2, tm0, np, K, KC, tid);

    const int r0 = wm * 64 + g;

    for (int c = 0; c < KC; c++) {
        const int rem = KC - 1 - c;
        if (rem >= 2)      asm volatile("cp.async.wait_group 2;" ::: "memory");
        else if (rem == 1) asm volatile("cp.async.wait_group 1;" ::: "memory");
        else               asm volatile("cp.async.wait_group 0;" ::: "memory");
        __syncthreads();

        const float* As = sm + (c & 3) * GST;
        const float* Bs = As + 9216;

#pragma unroll
        for (int ks = 0; ks < 4; ks++) {
            const int c0 = ks * 8 + t;
            uint32_t af[4][4];
#pragma unroll
            for (int mt = 0; mt < 4; mt++) {
                const int rb = (r0 + mt * 16) * 36;
                af[mt][0] = to_tf32(As[rb + c0]);
                af[mt][1] = to_tf32(As[rb + 8 * 36 + c0]);
                af[mt][2] = to_tf32(As[rb + c0 + 4]);
                af[mt][3] = to_tf32(As[rb + 8 * 36 + c0 + 4]);
            }
#pragma unroll
            for (int nt = 0; nt < 8; nt++) {
                uint2 bf = *(const uint2*)&Bs[(((wn * 8 + nt) * 4 + ks) * 32 + lane) * 2];
                mma168(acc[0][nt], af[0], bf);
                mma168(acc[1][nt], af[1], bf);
                mma168(acc[2][nt], af[2], bf);
                mma168(acc[3][nt], af[3], bf);
            }
        }

        if (c + 3 < KC)
            gemm_issue(A, Bp, sb, c + 3, tm0, np, K, KC, tid);
    }

    float* Cd; int ldc, coff;
    if (!fused)            { Cd = C0; ldc = N;    coff = 0;    }
    else if (tn0 < 2048)   { Cd = C0; ldc = 2048; coff = 0;    }
    else if (tn0 < 2560)   { Cd = C1; ldc = 512;  coff = 2048; }
    else                   { Cd = C2; ldc = 512;  coff = 2560; }

#pragma unroll
    for (int mt = 0; mt < 4; mt++) {
#pragma unroll
        for (int nt = 0; nt < 8; nt++) {
            int row = tm0 + wm * 64 + mt * 16 + g;
            int col = tn0 + wn * 64 + nt * 8 + t * 2 - coff;
            float4 a = acc[mt][nt];
            *(float2*)&Cd[(size_t)row * ldc + col] = make_float2(a.x, a.y);
            *(float2*)&Cd[(size_t)(row + 8) * ldc + col] = make_float2(a.z, a.w);
        }
    }
}

// ---------------------------------------------------------------------------
// RoPE on q (folds in 1/sqrt(HD) scale) and k, in place.
// ---------------------------------------------------------------------------
__global__ void rope_kernel(float* __restrict__ q, float* __restrict__ k)
{
    const int NQ = BATCH * SQ * NH * 64;
    const int NK = BATCH * SQ * NKV * 64;
    int i = blockIdx.x * blockDim.x + threadIdx.x;
    if (i >= NQ + NK) return;

    float* base;
    int d, s;
    float scale;
    if (i < NQ) {
        d = i & 63;
        int rest = i >> 6;
        s = (rest >> 4) & (SQ - 1);
        base = q + (size_t)rest * HD;
        scale = 0.08838834764831845f;
    } else {
        int j = i - NQ;
        d = j & 63;
        int rest = j >> 6;
        s = (rest >> 2) & (SQ - 1);
        base = k + (size_t)rest * HD;
        scale = 1.0f;
    }
    float inv_freq = powf(10000.0f, -(float)d * (1.0f / 64.0f));
    float ang = (float)s * inv_freq;
    float c = cosf(ang), sn = sinf(ang);
    float a = base[d], b = base[d + 64];
    base[d]      = (a * c - b * sn) * scale;
    base[d + 64] = (b * c + a * sn) * scale;
}

// ---------------------------------------------------------------------------
// Tensor-core flash attention v2 (tf32 mma) — staging FIXED to full tiles.
// CTA = 128 q-rows of one (b,h); 8 warps. K double-buffered.
// V staged in regs during S-mma, committed right after sync1;
// next-K staged during softmax, committed before sync2.
// ---------------------------------------------------------------------------
#define QS_OFF 0
#define K0_OFF 16896
#define K1_OFF 25344
#define VS_OFF 33792
#define PS_OFF 42496
#define MB_OFF 51200
#define LB_OFF 51456
#define ATT_SMEM (51712 * 4)

__global__ __launch_bounds__(256, 1) void attn_mma(
    const float* __restrict__ q, const float* __restrict__ k,
    const float* __restrict__ v, float* __restrict__ out)
{
    extern __shared__ float sm[];
    uint32_t* smu = (uint32_t*)sm;
    const int tid = threadIdx.x;
    const int lane = tid & 31, wid = tid >> 5;
    const int g = lane >> 2, t = lane & 3;
    const int wm = wid & 3, wn = wid >> 2;
    const int qt = gridDim.x - 1 - blockIdx.x;   // LPT: heavy tiles first
    const int h = blockIdx.y, b = blockIdx.z;
    const int kvh = h >> 2;
    const int q0 = qt * 128;

    const float4* q4 = (const float4*)q;
    const float4* k4 = (const float4*)k;
    const float4* v4 = (const float4*)v;

    const int ldrow = tid >> 5, ldc = tid & 31;  // 8 rows/pass x 32 float4

    // ---- prologue: Q tile (tf32) + K tile 0 into K0 ----
#pragma unroll
    for (int i = 0; i < 16; i++) {
        int f = i * 256 + tid;
        int row = f >> 5, c = f & 31;
        float4 vv = q4[((size_t)(b * SQ + q0 + row) * NH + h) * 32 + c];
        *(uint4*)&smu[QS_OFF + row * 132 + c * 4] = cvt4(vv);
    }
#pragma unroll
    for (int i = 0; i < 8; i++) {
        int row = i * 8 + ldrow;
        float4 kv = k4[((size_t)(b * SQ + row) * NKV + kvh) * 32 + ldc];
        *(uint4*)&smu[K0_OFF + row * 132 + ldc * 4] = cvt4(kv);
    }
    __syncthreads();

    float4 oacc[2][8];
#pragma unroll
    for (int i = 0; i < 2; i++)
#pragma unroll
        for (int j = 0; j < 8; j++) oacc[i][j] = make_float4(0.f, 0.f, 0.f, 0.f);
    float m_s[2][2] = {{-1e30f, -1e30f}, {-1e30f, -1e30f}};
    float l_s[2][2] = {{0.f, 0.f}, {0.f, 0.f}};

    const int r0 = wm * 32 + g;
    const int ntiles = 2 * qt + 2;

    for (int kt = 0; kt < ntiles; kt++) {
        const int k0 = kt * 64;
        const int KB = (kt & 1) ? K1_OFF : K0_OFF;

        // (1) stage V(kt): FULL 64x128 tile, 8 float4/thread
        float4 vreg[8];
#pragma unroll
        for (int i = 0; i < 8; i++)
            vreg[i] = v4[((size_t)(b * SQ + k0 + i * 8 + ldrow) * NKV + kvh) * 32 + ldc];

        // (2) S = Q @ K^T
        float4 sacc[2][4];
#pragma unroll
        for (int i = 0; i < 2; i++)
#pragma unroll
            for (int j = 0; j < 4; j++) sacc[i][j] = make_float4(0.f, 0.f, 0.f, 0.f);
#pragma unroll
        for (int ks = 0; ks < 16; ks++) {
            const int c0 = ks * 8 + t;
            uint32_t af[2][4];
#pragma unroll
            for (int mt = 0; mt < 2; mt++) {
                int rb = QS_OFF + (r0 + mt * 16) * 132 + c0;
                af[mt][0] = smu[rb];
                af[mt][1] = smu[rb + 132 * 8];
                af[mt][2] = smu[rb + 4];
                af[mt][3] = smu[rb + 132 * 8 + 4];
            }
#pragma unroll
            for (int nt = 0; nt < 4; nt++) {
                int nb = KB + (wn * 32 + nt * 8 + g) * 132 + c0;
                uint2 bf = make_uint2(smu[nb], smu[nb + 4]);
                mma168(sacc[0][nt], af[0], bf);
                mma168(sacc[1][nt], af[1], bf);
            }
        }

        // (3) causal mask (diagonal tiles) + row max -> MB
        if (kt >= 2 * qt) {
#pragma unroll
            for (int mt = 0; mt < 2; mt++)
#pragma unroll
                for (int nt = 0; nt < 4; nt++) {
                    int colb = k0 + wn * 32 + nt * 8 + 2 * t;
                    int rowb = q0 + wm * 32 + mt * 16 + g;
                    float* sc = (float*)&sacc[mt][nt];
                    if (colb     > rowb)     sc[0] = -1e30f;
                    if (colb + 1 > rowb)     sc[1] = -1e30f;
                    if (colb     > rowb + 8) sc[2] = -1e30f;
                    if (colb + 1 > rowb + 8) sc[3] = -1e30f;
                }
        }
        float rmax[2][2] = {{-1e30f, -1e30f}, {-1e30f, -1e30f}};
#pragma unroll
        for (int mt = 0; mt < 2; mt++)
#pragma unroll
            for (int nt = 0; nt < 4; nt++) {
                float4 s4 = sacc[mt][nt];
                rmax[mt][0] = fmaxf(rmax[mt][0], fmaxf(s4.x, s4.y));
                rmax[mt][1] = fmaxf(rmax[mt][1], fmaxf(s4.z, s4.w));
            }
#pragma unroll
        for (int mt = 0; mt < 2; mt++)
#pragma unroll
            for (int hf = 0; hf < 2; hf++) {
                float x = rmax[mt][hf];
                x = fmaxf(x, __shfl_xor_sync(0xffffffffu, x, 1));
                x = fmaxf(x, __shfl_xor_sync(0xffffffffu, x, 2));
                rmax[mt][hf] = x;
            }
        if (t == 0) {
#pragma unroll
            for (int mt = 0; mt < 2; mt++)
#pragma unroll
                for (int hf = 0; hf < 2; hf++)
                    sm[MB_OFF + wn * 128 + wm * 32 + mt * 16 + hf * 8 + g] = rmax[mt][hf];
        }
        __syncthreads();   // sync1: MB visible; old V/K buffers free

        // (4) commit V to smem (frees vreg)
#pragma unroll
        for (int i = 0; i < 8; i++)
            *(uint4*)&smu[VS_OFF + (i * 8 + ldrow) * 136 + ldc * 4] = cvt4(vreg[i]);

        // (5) stage K(kt+1) (latency hidden by softmax below)
        float4 kreg[8];
        const bool havek = (kt + 1 < ntiles);
        if (havek) {
#pragma unroll
            for (int i = 0; i < 8; i++)
                kreg[i] = k4[((size_t)(b * SQ + k0 + 64 + i * 8 + ldrow) * NKV + kvh) * 32 + ldc];
        }

        // (6) softmax: alpha, exp, publish P + LB, rescale O
        float alpha[2][2];
#pragma unroll
        for (int mt = 0; mt < 2; mt++)
#pragma unroll
            for (int hf = 0; hf < 2; hf++) {
                int row = wm * 32 + mt * 16 + hf * 8 + g;
                float mn = fmaxf(m_s[mt][hf],
                                 fmaxf(sm[MB_OFF + row], sm[MB_OFF + 128 + row]));
                alpha[mt][hf] = __expf(m_s[mt][hf] - mn);
                m_s[mt][hf] = mn;
            }
        float rsum[2][2] = {{0.f, 0.f}, {0.f, 0.f}};
#pragma unroll
        for (int mt = 0; mt < 2; mt++)
#pragma unroll
            for (int nt = 0; nt < 4; nt++) {
                float4 s4 = sacc[mt][nt];
                float p0 = __expf(s4.x - m_s[mt][0]);
                float p1 = __expf(s4.y - m_s[mt][0]);
                float p2 = __expf(s4.z - m_s[mt][1]);
                float p3 = __expf(s4.w - m_s[mt][1]);
                rsum[mt][0] += p0 + p1;
                rsum[mt][1] += p2 + p3;
                int cb = wn * 32 + nt * 8 + 2 * t;
                int rl = wm * 32 + mt * 16 + g;
                *(uint2*)&smu[PS_OFF + rl * 68 + cb] =
                    make_uint2(to_tf32(p0), to_tf32(p1));
                *(uint2*)&smu[PS_OFF + (rl + 8) * 68 + cb] =
                    make_uint2(to_tf32(p2), to_tf32(p3));
            }
#pragma unroll
        for (int mt = 0; mt < 2; mt++)
#pragma unroll
            for (int hf = 0; hf < 2; hf++) {
                float x = rsum[mt][hf];
                x += __shfl_xor_sync(0xffffffffu, x, 1);
                x += __shfl_xor_sync(0xffffffffu, x, 2);
                rsum[mt][hf] = x;
            }
        if (t == 0) {
#pragma unroll
            for (int mt = 0; mt < 2; mt++)
#pragma unroll
                for (int hf = 0; hf < 2; hf++)
                    sm[LB_OFF + wn * 128 + wm * 32 + mt * 16 + hf * 8 + g] = rsum[mt][hf];
        }
#pragma unroll
        for (int mt = 0; mt < 2; mt++)
#pragma unroll
            for (int nt = 0; nt < 8; nt++) {
                oacc[mt][nt].x *= alpha[mt][0];
                oacc[mt][nt].y *= alpha[mt][0];
                oacc[mt][nt].z *= alpha[mt][1];
                oacc[mt][nt].w *= alpha[mt][1];
            }

        // (7) commit K(kt+1)
        const int KBn = (kt & 1) ? K0_OFF : K1_OFF;
        if (havek) {
#pragma unroll
            for (int i = 0; i < 8; i++)
                *(uint4*)&smu[KBn + (i * 8 + ldrow) * 132 + ldc * 4] = cvt4(kreg[i]);
        }
        __syncthreads();   // sync2: P, LB, V, K(next) visible

        // (8) l update + O += P @ V
#pragma unroll
        for (int mt = 0; mt < 2; mt++)
#pragma unroll
            for (int hf = 0; hf < 2; hf++) {
                int row = wm * 32 + mt * 16 + hf * 8 + g;
                l_s[mt][hf] = l_s[mt][hf] * alpha[mt][hf]
                            + sm[LB_OFF + row] + sm[LB_OFF + 128 + row];
            }
#pragma unroll
        for (int ks = 0; ks < 8; ks++) {
            const int c0 = ks * 8 + t;
            uint32_t af[2][4];
#pragma unroll
            for (int mt = 0; mt < 2; mt++) {
                int rb = PS_OFF + (r0 + mt * 16) * 68 + c0;
                af[mt][0] = smu[rb];
                af[mt][1] = smu[rb + 68 * 8];
                af[mt][2] = smu[rb + 4];
                af[mt][3] = smu[rb + 68 * 8 + 4];
            }
#pragma unroll
            for (int nt = 0; nt < 8; nt++) {
                int nb = VS_OFF + c0 * 136 + wn * 64 + nt * 8 + g;
                uint2 bf = make_uint2(smu[nb], smu[nb + 4 * 136]);
                mma168(oacc[0][nt], af[0], bf);
                mma168(oacc[1][nt], af[1], bf);
            }
        }
    }

    // ---- epilogue ----
#pragma unroll
    for (int mt = 0; mt < 2; mt++) {
        float i0 = 1.f / l_s[mt][0], i1 = 1.f / l_s[mt][1];
#pragma unroll
        for (int nt = 0; nt < 8; nt++) {
            int row = q0 + wm * 32 + mt * 16 + g;
            int col = h * HD + wn * 64 + nt * 8 + 2 * t;
            float4 o = oacc[mt][nt];
            *(float2*)&out[(size_t)(b * SQ + row) * EB + col] =
                make_float2(o.x * i0, o.y * i0);
            *(float2*)&out[(size_t)(b * SQ + row + 8) * EB + col] =
                make_float2(o.z * i1, o.w * i1);
        }
    }
}

// ---------------------------------------------------------------------------
extern "C" void kernel_launch(void* const* d_in, const int* in_sizes, int n_in,
                              void* d_out, int out_size)
{
    const float* x  = (const float*)d_in[0];
    const float* Wq = (const float*)d_in[1];
    const float* Wk = (const float*)d_in[2];
    const float* Wv = (const float*)d_in[3];
    const float* Wo = (const float*)d_in[4];

    float *qb, *kb, *vb, *ab, *wt;
    cudaGetSymbolAddress((void**)&qb, g_q);
    cudaGetSymbolAddress((void**)&kb, g_k);
    cudaGetSymbolAddress((void**)&vb, g_v);
    cudaGetSymbolAddress((void**)&ab, g_attn);
    cudaGetSymbolAddress((void**)&wt, g_wt);

    const int M = BATCH * SQ;   // 4096

    cudaFuncSetAttribute(gemm_mma, cudaFuncAttributeMaxDynamicSharedMemorySize,
                         GEMM_SMEM);
    cudaFuncSetAttribute(attn_mma, cudaFuncAttributeMaxDynamicSharedMemorySize,
                         ATT_SMEM);

    // Pack Q|K|V weights into one fragment buffer (np blocks of 128 cols)
    pack_b<<<(EB * EB / 2 + 255) / 256, 256>>>(Wq, wt, EB, EB);
    pack_b<<<(EB * KVDIM / 2 + 255) / 256, 256>>>(Wk, wt + 16 * 262144, EB, KVDIM);
    pack_b<<<(EB * KVDIM / 2 + 255) / 256, 256>>>(Wv, wt + 20 * 262144, EB, KVDIM);

    // Fused QKV projection: N = 2048 + 512 + 512 = 3072
    gemm_mma<<<dim3(3072 / 128, M / 256), 256, GEMM_SMEM>>>(
        x, wt, qb, kb, vb, M, 3072, EB, 1);

    // RoPE (+ q scaling)
    int npairs = BATCH * SQ * (NH + NKV) * 64;
    rope_kernel<<<(npairs + 255) / 256, 256>>>(qb, kb);

    // Tensor-core flash attention
    attn_mma<<<dim3(SQ / 128, NH, BATCH), 256, ATT_SMEM>>>(qb, kb, vb, ab);

    // Output projection
    pack_b<<<(EB * EB / 2 + 255) / 256, 256>>>(Wo, wt, EB, EB);
    gemm_mma<<<dim3(EB / 128, M / 256), 256, GEMM_SMEM>>>(
        ab, wt, (float*)d_out, nullptr, nullptr, M, EB, EB, 0);
}